// round 7
// baseline (speedup 1.0000x reference)
#include <cuda_runtime.h>

// Bilinear 2x upsample, half_pixel_centers=False (asymmetric: h = hd/2).
// Input : (16, 64, 128, 128) fp32, Output: (16, 64, 256, 256) fp32.
//
// Stencil (exact, neighbors clamped at 127):
//   out[2i  ][2j  ] = x[i][j]
//   out[2i  ][2j+1] = (x[i][j] + x[i][j+1]) / 2
//   odd output rows = average of adjacent even-row expansions (H is linear)
//
// One warp per input ROW PAIR (2r, 2r+1): loads rows 2r, 2r+1, 2r+2 (clamped),
// emits output rows 4r..4r+3. 6 coalesced float2 loads, 8 fully-coalesced
// 512B float4 warp stores.
//
// R7 change vs R6: plain write-back stores (no __stcs). Single-variable
// experiment: is the evict-first streaming policy throttling the L2->DRAM
// write path? Everything else identical.

static constexpr int SRC_H = 128;
static constexpr int SRC_W = 128;
static constexpr int NC    = 16 * 64;   // 1024
static constexpr int DST_W = 256;

struct RowData {
    float2 v0, v1;   // cols (2l, 2l+1) and (64+2l, 64+2l+1)
    float  n0, n1;   // right neighbors: cols 2l+2 and 64+2l+2 (clamped)
};

__device__ __forceinline__ void h_expand(const RowData& r, float4& e0, float4& e1) {
    e0 = make_float4(r.v0.x, 0.5f * (r.v0.x + r.v0.y),
                     r.v0.y, 0.5f * (r.v0.y + r.n0));
    e1 = make_float4(r.v1.x, 0.5f * (r.v1.x + r.v1.y),
                     r.v1.y, 0.5f * (r.v1.y + r.n1));
}

__device__ __forceinline__ float4 avg4(const float4& a, const float4& b) {
    return make_float4(0.5f * (a.x + b.x), 0.5f * (a.y + b.y),
                       0.5f * (a.z + b.z), 0.5f * (a.w + b.w));
}

__global__ void __launch_bounds__(256)
bilinear2x_kernel(const float* __restrict__ in, float* __restrict__ out) {
    const unsigned F = 0xffffffffu;
    const int warp_global = blockIdx.x * (blockDim.x >> 5) + (threadIdx.x >> 5);
    const int lane = threadIdx.x & 31;

    const int nc = warp_global >> 6;        // / 64 row-pairs per image
    const int r  = warp_global & 63;        // row-pair index
    const int iA = 2 * r;
    const int iB = 2 * r + 1;
    const int iC = (iB < SRC_H - 1) ? (iB + 1) : iB;   // clamp bottom

    const float* img = in + (size_t)nc * (SRC_H * SRC_W);
    const float2* rowA = reinterpret_cast<const float2*>(img + iA * SRC_W);
    const float2* rowB = reinterpret_cast<const float2*>(img + iB * SRC_W);
    const float2* rowC = reinterpret_cast<const float2*>(img + iC * SRC_W);

    // Front-batch all 6 independent coalesced loads (256B warp transactions)
    RowData A, B, C;
    A.v0 = __ldg(rowA + lane);      A.v1 = __ldg(rowA + 32 + lane);
    B.v0 = __ldg(rowB + lane);      B.v1 = __ldg(rowB + 32 + lane);
    C.v0 = __ldg(rowC + lane);      C.v1 = __ldg(rowC + 32 + lane);

    const int nxt = (lane + 1) & 31;

    // Right-neighbor resolution per row:
    //   half 0: lanes 0..30 -> lane+1's v0.x ; lane 31 -> col 64 = lane 0's v1.x
    //   half 1: lanes 0..30 -> lane+1's v1.x ; lane 31 -> clamp to own v1.y
    {
        float s0 = __shfl_sync(F, A.v0.x, nxt);
        float s1 = __shfl_sync(F, A.v1.x, nxt);
        float t  = __shfl_sync(F, A.v1.x, 0);
        A.n0 = (lane == 31) ? t : s0;
        A.n1 = (lane == 31) ? A.v1.y : s1;
    }
    {
        float s0 = __shfl_sync(F, B.v0.x, nxt);
        float s1 = __shfl_sync(F, B.v1.x, nxt);
        float t  = __shfl_sync(F, B.v1.x, 0);
        B.n0 = (lane == 31) ? t : s0;
        B.n1 = (lane == 31) ? B.v1.y : s1;
    }
    {
        float s0 = __shfl_sync(F, C.v0.x, nxt);
        float s1 = __shfl_sync(F, C.v1.x, nxt);
        float t  = __shfl_sync(F, C.v1.x, 0);
        C.n0 = (lane == 31) ? t : s0;
        C.n1 = (lane == 31) ? C.v1.y : s1;
    }

    // Horizontal expansions of the three input rows
    float4 eA0, eA1, eB0, eB1, eC0, eC1;
    h_expand(A, eA0, eA1);
    h_expand(B, eB0, eB1);
    h_expand(C, eC0, eC1);

    float* outImg = out + (size_t)nc * (2 * SRC_H * DST_W);
    float4* o0 = reinterpret_cast<float4*>(outImg + (4 * r + 0) * DST_W);
    float4* o1 = reinterpret_cast<float4*>(outImg + (4 * r + 1) * DST_W);
    float4* o2 = reinterpret_cast<float4*>(outImg + (4 * r + 2) * DST_W);
    float4* o3 = reinterpret_cast<float4*>(outImg + (4 * r + 3) * DST_W);

    // 8 fully-coalesced 512B warp stores, default write-back policy
    o0[lane]      = eA0;
    o0[32 + lane] = eA1;
    o1[lane]      = avg4(eA0, eB0);
    o1[32 + lane] = avg4(eA1, eB1);
    o2[lane]      = eB0;
    o2[32 + lane] = eB1;
    o3[lane]      = avg4(eB0, eC0);
    o3[32 + lane] = avg4(eB1, eC1);
}

extern "C" void kernel_launch(void* const* d_in, const int* in_sizes, int n_in,
                              void* d_out, int out_size) {
    const float* x = (const float*)d_in[0];
    float* out = (float*)d_out;

    const int total_warps = NC * (SRC_H / 2);         // 65536 row-pairs
    const int threads = 256;                          // 8 warps/block
    const int blocks = total_warps / (threads / 32);  // 8192

    bilinear2x_kernel<<<blocks, threads>>>(x, out);
}

// round 8
// speedup vs baseline: 1.0122x; 1.0122x over previous
#include <cuda_runtime.h>
#include <cstdint>

// Bilinear 2x upsample, half_pixel_centers=False. fp32 (16,64,128,128)->(16,64,256,256).
//
// R8 experiment: SMEM-staged bulk stores. Per-warp STG plateaued at ~5.5TB/s
// DRAM write bandwidth (67.5% of peak) across 3 structural variants. Theory:
// warp-granular 512B store slices give DRAM short interleaved write bursts.
// Here each block computes 32 contiguous output rows (32KB) into SMEM and
// drains them with ONE cp.async.bulk S2G -> long sequential DRAM bursts.
//
// Block = 256 threads (8 warps), handles 16 input rows of one image:
//   warp w: input rows (base+2w, +1, +2 clamped) -> SMEM output rows 4w..4w+3
// Then: __syncthreads -> fence.proxy.async -> 32KB cp.async.bulk -> wait_group.read.
// Cross-block overlap (7 blocks/SM resident) hides the per-block drain tail.

static constexpr int SRC_H = 128;
static constexpr int SRC_W = 128;
static constexpr int NC    = 16 * 64;       // 1024
static constexpr int DST_W = 256;
static constexpr int IN_ROWS_PER_BLK  = 16;
static constexpr int CHUNKS_PER_IMG   = SRC_H / IN_ROWS_PER_BLK;   // 8
static constexpr int OUT_ROWS_PER_BLK = 2 * IN_ROWS_PER_BLK;       // 32
static constexpr int SMEM_F4 = OUT_ROWS_PER_BLK * DST_W / 4;       // 2048 float4 = 32KB

struct RowData {
    float2 v0, v1;   // cols (2l, 2l+1) and (64+2l, 64+2l+1)
    float  n0, n1;   // right neighbors (clamped)
};

__device__ __forceinline__ void h_expand(const RowData& r, float4& e0, float4& e1) {
    e0 = make_float4(r.v0.x, 0.5f * (r.v0.x + r.v0.y),
                     r.v0.y, 0.5f * (r.v0.y + r.n0));
    e1 = make_float4(r.v1.x, 0.5f * (r.v1.x + r.v1.y),
                     r.v1.y, 0.5f * (r.v1.y + r.n1));
}

__device__ __forceinline__ float4 avg4(const float4& a, const float4& b) {
    return make_float4(0.5f * (a.x + b.x), 0.5f * (a.y + b.y),
                       0.5f * (a.z + b.z), 0.5f * (a.w + b.w));
}

__global__ void __launch_bounds__(256)
bilinear2x_bulk_kernel(const float* __restrict__ in, float* __restrict__ out) {
    __shared__ float4 stage[SMEM_F4];   // 32KB: 32 output rows x 256 floats

    const unsigned F = 0xffffffffu;
    const int lane = threadIdx.x & 31;
    const int w    = threadIdx.x >> 5;          // warp in block = row-pair index

    const int bid = blockIdx.x;
    const int nc  = bid >> 3;                   // / CHUNKS_PER_IMG
    const int t   = bid & (CHUNKS_PER_IMG - 1); // chunk within image

    const int iA = t * IN_ROWS_PER_BLK + 2 * w;     // input rows
    const int iB = iA + 1;
    const int iC = (iB < SRC_H - 1) ? (iB + 1) : iB;

    const float* img = in + (size_t)nc * (SRC_H * SRC_W);
    const float2* rowA = reinterpret_cast<const float2*>(img + iA * SRC_W);
    const float2* rowB = reinterpret_cast<const float2*>(img + iB * SRC_W);
    const float2* rowC = reinterpret_cast<const float2*>(img + iC * SRC_W);

    RowData A, B, C;
    A.v0 = __ldg(rowA + lane);   A.v1 = __ldg(rowA + 32 + lane);
    B.v0 = __ldg(rowB + lane);   B.v1 = __ldg(rowB + 32 + lane);
    C.v0 = __ldg(rowC + lane);   C.v1 = __ldg(rowC + 32 + lane);

    const int nxt = (lane + 1) & 31;
    {
        float s0 = __shfl_sync(F, A.v0.x, nxt);
        float s1 = __shfl_sync(F, A.v1.x, nxt);
        float tt = __shfl_sync(F, A.v1.x, 0);
        A.n0 = (lane == 31) ? tt : s0;
        A.n1 = (lane == 31) ? A.v1.y : s1;
    }
    {
        float s0 = __shfl_sync(F, B.v0.x, nxt);
        float s1 = __shfl_sync(F, B.v1.x, nxt);
        float tt = __shfl_sync(F, B.v1.x, 0);
        B.n0 = (lane == 31) ? tt : s0;
        B.n1 = (lane == 31) ? B.v1.y : s1;
    }
    {
        float s0 = __shfl_sync(F, C.v0.x, nxt);
        float s1 = __shfl_sync(F, C.v1.x, nxt);
        float tt = __shfl_sync(F, C.v1.x, 0);
        C.n0 = (lane == 31) ? tt : s0;
        C.n1 = (lane == 31) ? C.v1.y : s1;
    }

    float4 eA0, eA1, eB0, eB1, eC0, eC1;
    h_expand(A, eA0, eA1);
    h_expand(B, eB0, eB1);
    h_expand(C, eC0, eC1);

    // Stage 4 output rows (4w..4w+3) into SMEM; conflict-free STS.128
    float4* s0 = stage + (4 * w + 0) * (DST_W / 4);
    float4* s1 = stage + (4 * w + 1) * (DST_W / 4);
    float4* s2 = stage + (4 * w + 2) * (DST_W / 4);
    float4* s3 = stage + (4 * w + 3) * (DST_W / 4);
    s0[lane]      = eA0;
    s0[32 + lane] = eA1;
    s1[lane]      = avg4(eA0, eB0);
    s1[32 + lane] = avg4(eA1, eB1);
    s2[lane]      = eB0;
    s2[32 + lane] = eB1;
    s3[lane]      = avg4(eB0, eC0);
    s3[32 + lane] = avg4(eB1, eC1);

    __syncthreads();

    // One 32KB bulk store: SMEM -> contiguous 32 output rows in GMEM
    if (threadIdx.x == 0) {
        float* dst = out + ((size_t)nc * (2 * SRC_H) + (size_t)t * OUT_ROWS_PER_BLK) * DST_W;
        uint32_t saddr = (uint32_t)__cvta_generic_to_shared(stage);
        asm volatile("fence.proxy.async.shared::cta;" ::: "memory");
        asm volatile(
            "cp.async.bulk.global.shared::cta.bulk_group [%0], [%1], %2;"
            :: "l"(dst), "r"(saddr), "n"(OUT_ROWS_PER_BLK * DST_W * 4)
            : "memory");
        asm volatile("cp.async.bulk.commit_group;" ::: "memory");
        // Wait until the async engine has READ the SMEM (safe to exit/reuse);
        // the global writes complete asynchronously.
        asm volatile("cp.async.bulk.wait_group.read 0;" ::: "memory");
    }
    __syncthreads();
}

extern "C" void kernel_launch(void* const* d_in, const int* in_sizes, int n_in,
                              void* d_out, int out_size) {
    const float* x = (const float*)d_in[0];
    float* out = (float*)d_out;

    const int blocks = NC * CHUNKS_PER_IMG;   // 8192
    bilinear2x_bulk_kernel<<<blocks, 256>>>(x, out);
}